// round 9
// baseline (speedup 1.0000x reference)
#include <cuda_runtime.h>
#include <cuda_fp16.h>
#include <cstdint>
#include <cstddef>

#define B_   16
#define H_   64
#define W_   64
#define C_   256
#define NDIM 256
#define NTILES 16384                 // 16 * 32 * 32 (2x2 output tiles)
#define TILEC  ((size_t)NTILES * 256)

// GEMM tiling (K = 256 per Winograd point; CTA loops a=0..3 for fixed b)
#define KD2  256
#define BM 64
#define BN 128
#define BK 64
#define NIT 16                       // 4 a-values x 4 BK-chunks
#define NSTAGE 4
#define A_BYTES (BM * 128)
#define B_BYTES (BN * 128)
#define STAGE_BYTES (A_BYTES + B_BYTES)   // 24 KB
#define SM_TOTAL (NSTAGE * STAGE_BYTES)   // 96 KB (2 CTAs/SM = 192 KB)

__device__ __align__(16) float  Mf[(size_t)C_ * 256 * 8];          // [c][o][d] 2 MB
__device__ __align__(16) __half U_buf[(size_t)16 * 256 * 256];     // [k][o][c] 2 MB
__device__ __align__(16) __half V_buf[(size_t)16 * TILEC];         // [k][tile][c] 128 MB
__device__ __align__(16) __half Tw[(size_t)8 * TILEC];             // [b*2+p][tile][o] 64 MB

// ---------------------------------------------------------------------------
__device__ __forceinline__ uint32_t smem_u32(const void* p) {
    uint32_t a;
    asm("{ .reg .u64 t; cvta.to.shared.u64 t, %1; cvt.u32.u64 %0, t; }" : "=r"(a) : "l"(p));
    return a;
}
__device__ __forceinline__ void cp_async16(uint32_t dst, const void* src) {
    asm volatile("cp.async.cg.shared.global [%0], [%1], 16;" :: "r"(dst), "l"(src));
}
__device__ __forceinline__ void cp_commit() {
    asm volatile("cp.async.commit_group;" ::: "memory");
}
template<int N> __device__ __forceinline__ void cp_wait() {
    asm volatile("cp.async.wait_group %0;" :: "n"(N) : "memory");
}
__device__ __forceinline__ void ldsm4(uint32_t& r0, uint32_t& r1, uint32_t& r2, uint32_t& r3,
                                      uint32_t addr) {
    asm volatile("ldmatrix.sync.aligned.m8n8.x4.shared.b16 {%0,%1,%2,%3}, [%4];"
                 : "=r"(r0), "=r"(r1), "=r"(r2), "=r"(r3) : "r"(addr));
}
__device__ __forceinline__ void mma16816(float* d, const uint32_t* a, const uint32_t* b) {
    asm volatile(
        "mma.sync.aligned.m16n8k16.row.col.f32.f16.f16.f32 "
        "{%0,%1,%2,%3}, {%4,%5,%6,%7}, {%8,%9}, {%0,%1,%2,%3};\n"
        : "+f"(d[0]), "+f"(d[1]), "+f"(d[2]), "+f"(d[3])
        : "r"(a[0]), "r"(a[1]), "r"(a[2]), "r"(a[3]), "r"(b[0]), "r"(b[1]));
}
__device__ __forceinline__ float4 f4add(float4 a, float4 b) {
    return make_float4(a.x + b.x, a.y + b.y, a.z + b.z, a.w + b.w);
}
__device__ __forceinline__ float4 f4sub(float4 a, float4 b) {
    return make_float4(a.x - b.x, a.y - b.y, a.z - b.z, a.w - b.w);
}

// ---------------------------------------------------------------------------
// Kernel 1: fold weights -> Mf[c][o][d] (fp32)
// ---------------------------------------------------------------------------
__global__ void fold_weights_kernel(const float* __restrict__ Wd,
                                    const float* __restrict__ Wc)
{
    const int bid = blockIdx.x;
    const int d  = bid >> 4;
    const int ct = (bid >> 2) & 3;
    const int et = bid & 3;

    __shared__ float WdS[64][33];
    __shared__ float WcS[64][33];

    const int t  = threadIdx.x;
    const int tx = t & 15;
    const int ty = t >> 4;

    float acc[4][4];
    #pragma unroll
    for (int i = 0; i < 4; i++)
        #pragma unroll
        for (int j = 0; j < 4; j++) acc[i][j] = 0.0f;

    const float* WdBase = Wd + (size_t)d * C_ * C_ + (size_t)(ct * 64) * C_;
    const float* WcBase = Wc + (size_t)(et * 64) * (8 * C_) + d * C_;

    const int ci  = t >> 2;
    const int kk0 = (t & 3) * 8;

    for (int k0 = 0; k0 < C_; k0 += 32) {
        const float* srcA = WdBase + (size_t)ci * C_        + k0 + kk0;
        const float* srcB = WcBase + (size_t)ci * (8 * C_)  + k0 + kk0;
        #pragma unroll
        for (int u = 0; u < 8; u++) WdS[ci][kk0 + u] = srcA[u];
        #pragma unroll
        for (int u = 0; u < 8; u++) WcS[ci][kk0 + u] = srcB[u];
        __syncthreads();
        #pragma unroll
        for (int kk = 0; kk < 32; kk++) {
            float a[4], bb[4];
            #pragma unroll
            for (int i = 0; i < 4; i++) a[i]  = WdS[ty * 4 + i][kk];
            #pragma unroll
            for (int j = 0; j < 4; j++) bb[j] = WcS[tx * 4 + j][kk];
            #pragma unroll
            for (int i = 0; i < 4; i++)
                #pragma unroll
                for (int j = 0; j < 4; j++) acc[i][j] += a[i] * bb[j];
        }
        __syncthreads();
    }
    #pragma unroll
    for (int i = 0; i < 4; i++) {
        const int c = ct * 64 + ty * 4 + i;
        #pragma unroll
        for (int j = 0; j < 4; j++) {
            const int o = et * 64 + tx * 4 + j;
            Mf[((size_t)c * 256 + o) * 8 + d] = acc[i][j];
        }
    }
}

// ---------------------------------------------------------------------------
// Kernel 2: weight transform U_k = G K G^T  (k = a*4+b), fp16 [k][o][c]
// ---------------------------------------------------------------------------
__global__ __launch_bounds__(256) void weight_transform_kernel()
{
    const int o = blockIdx.x;
    const int c = threadIdx.x;

    const float* mp = &Mf[((size_t)c * 256 + o) * 8];
    float m[8];
    const float4 f0 = *(const float4*)(mp);
    const float4 f1 = *(const float4*)(mp + 4);
    m[0]=f0.x; m[1]=f0.y; m[2]=f0.z; m[3]=f0.w;
    m[4]=f1.x; m[5]=f1.y; m[6]=f1.z; m[7]=f1.w;

    float K[3][3];
    K[0][0]=m[3]; K[0][1]=m[4]; K[0][2]=m[5];
    K[1][0]=m[2]; K[1][1]=0.f;  K[1][2]=m[6];
    K[2][0]=m[1]; K[2][1]=m[0]; K[2][2]=m[7];

    float T[4][3];
    #pragma unroll
    for (int j = 0; j < 3; j++) {
        T[0][j] = K[0][j];
        T[1][j] = 0.5f * (K[0][j] + K[1][j] + K[2][j]);
        T[2][j] = 0.5f * (K[0][j] - K[1][j] + K[2][j]);
        T[3][j] = K[2][j];
    }
    #pragma unroll
    for (int a = 0; a < 4; a++) {
        float U0 = T[a][0];
        float U1 = 0.5f * (T[a][0] + T[a][1] + T[a][2]);
        float U2 = 0.5f * (T[a][0] - T[a][1] + T[a][2]);
        float U3 = T[a][2];
        U_buf[(size_t)(a * 4 + 0) * 65536 + o * 256 + c] = __float2half(U0);
        U_buf[(size_t)(a * 4 + 1) * 65536 + o * 256 + c] = __float2half(U1);
        U_buf[(size_t)(a * 4 + 2) * 65536 + o * 256 + c] = __float2half(U2);
        U_buf[(size_t)(a * 4 + 3) * 65536 + o * 256 + c] = __float2half(U3);
    }
}

// ---------------------------------------------------------------------------
// Kernel 3: FUSED pad + input transform (fp32 grid -> fp16 V), float4/thread
// ---------------------------------------------------------------------------
__global__ __launch_bounds__(256) void input_transform_kernel(const float* __restrict__ g)
{
    const int tid  = threadIdx.x;
    const int tile = blockIdx.x * 4 + (tid >> 6);
    const int c    = (tid & 63) * 4;

    const int b  = tile >> 10;
    const int ty = (tile >> 5) & 31;
    const int tx = tile & 31;

    const int gy0 = 2 * ty - 1;
    const int gx0 = 2 * tx - 1;
    const float* gbase = g + ((size_t)b * H_ * W_) * C_ + c;

    float4 d[4][4];
    #pragma unroll
    for (int i = 0; i < 4; i++) {
        const int gy = gy0 + i;
        const bool vy = (gy >= 0) && (gy < H_);
        #pragma unroll
        for (int j = 0; j < 4; j++) {
            const int gx = gx0 + j;
            if (vy && gx >= 0 && gx < W_)
                d[i][j] = *(const float4*)(gbase + ((size_t)gy * W_ + gx) * C_);
            else
                d[i][j] = make_float4(0.0f, 0.0f, 0.0f, 0.0f);
        }
    }

    float4 tr[4][4];
    #pragma unroll
    for (int j = 0; j < 4; j++) {
        tr[0][j] = f4sub(d[0][j], d[2][j]);
        tr[1][j] = f4add(d[1][j], d[2][j]);
        tr[2][j] = f4sub(d[2][j], d[1][j]);
        tr[3][j] = f4sub(d[1][j], d[3][j]);
    }
    #pragma unroll
    for (int a = 0; a < 4; a++) {
        float4 V[4];
        V[0] = f4sub(tr[a][0], tr[a][2]);
        V[1] = f4add(tr[a][1], tr[a][2]);
        V[2] = f4sub(tr[a][2], tr[a][1]);
        V[3] = f4sub(tr[a][1], tr[a][3]);
        #pragma unroll
        for (int bb = 0; bb < 4; bb++) {
            __half2 lo = __floats2half2_rn(V[bb].x, V[bb].y);
            __half2 hi = __floats2half2_rn(V[bb].z, V[bb].w);
            uint2 u;
            u.x = *(uint32_t*)&lo;
            u.y = *(uint32_t*)&hi;
            *(uint2*)&V_buf[(size_t)(a * 4 + bb) * TILEC + (size_t)tile * 256 + c] = u;
        }
    }
}

// ---------------------------------------------------------------------------
// Kernel 4: GEMM with fused Winograd row-combine (4-stage cp.async).
// CTA = (m-block, n-half, b). Loops a=0..3: M_a = V_{a*4+b} @ U_{a*4+b}^T,
// folds into T_p = sum_a A_p[a] * M_a (fp16x2 accumulators), writes Tw.
// ---------------------------------------------------------------------------
__global__ __launch_bounds__(256, 2) void wino_gemm_T(void)
{
    extern __shared__ __align__(1024) char smem[];
    const uint32_t sbase = smem_u32(smem);

    const int t    = threadIdx.x;
    const int warp = t >> 5, lane = t & 31;
    const int bx   = blockIdx.x;
    const int n0   = (bx & 1) * BN;
    const int bfix = (bx >> 1) & 3;
    const int m0   = (bx >> 3) * BM;

    // ---- producer setup ----
    const int arow   = t >> 2;
    const int acpair = (t & 3) * 2;
    const int brow = t >> 1;
    const int bc0  = (t & 1) * 4;

    const __half* a_base = V_buf + (size_t)bfix * TILEC + (size_t)(m0 + arow) * KD2 + acpair * 8;
    const __half* b_base = U_buf + (size_t)bfix * 65536 + (size_t)(n0 + brow) * KD2 + bc0 * 8;

    uint32_t a_dst[2], b_dst[4];
    #pragma unroll
    for (int j = 0; j < 2; j++)
        a_dst[j] = (uint32_t)(arow * 128 + (((acpair + j) ^ (arow & 7)) << 4));
    #pragma unroll
    for (int j = 0; j < 4; j++)
        b_dst[j] = (uint32_t)(A_BYTES + brow * 128 + (((bc0 + j) ^ (brow & 7)) << 4));

    // ---- consumer setup: warp tile 32x32 ----
    const int wm = (warp >> 2) * 32;
    const int wn = (warp & 3) * 32;
    const int swz  = lane & 7;
    const int a_hi = lane >> 4;
    const int b_hi = (lane >> 3) & 1;

    uint32_t a_row_off[2], b_row_off[2];
    #pragma unroll
    for (int im = 0; im < 2; im++)
        a_row_off[im] = (uint32_t)((wm + im * 16 + (lane & 15)) * 128);
    #pragma unroll
    for (int j2 = 0; j2 < 2; j2++)
        b_row_off[j2] = (uint32_t)(A_BYTES +
            (wn + j2 * 16 + ((lane >> 4) << 3) + (lane & 7)) * 128);

    float acc[2][4][4];
    #pragma unroll
    for (int i = 0; i < 2; i++)
        #pragma unroll
        for (int j = 0; j < 4; j++)
            #pragma unroll
            for (int r = 0; r < 4; r++) acc[i][j][r] = 0.0f;

    __half2 Tacc[2][2][4][2];
    #pragma unroll
    for (int p = 0; p < 2; p++)
        #pragma unroll
        for (int i = 0; i < 2; i++)
            #pragma unroll
            for (int j = 0; j < 4; j++) {
                Tacc[p][i][j][0] = __half2half2(__float2half(0.0f));
                Tacc[p][i][j][1] = __half2half2(__float2half(0.0f));
            }

    #define LOAD_STAGE(I, S)                                                       \
    do {                                                                           \
        const int a_  = (I) >> 2;                                                  \
        const int kt_ = (I) & 3;                                                   \
        const __half* asrc = a_base + (size_t)(a_ * 4) * TILEC + kt_ * 64;         \
        const __half* bsrc = b_base + (size_t)(a_ * 4) * 65536 + kt_ * 64;         \
        const uint32_t sb  = sbase + (S) * STAGE_BYTES;                            \
        _Pragma("unroll")                                                          \
        for (int j = 0; j < 2; j++) cp_async16(sb + a_dst[j], asrc + j * 8);       \
        _Pragma("unroll")                                                          \
        for (int j = 0; j < 4; j++) cp_async16(sb + b_dst[j], bsrc + j * 8);       \
        cp_commit();                                                               \
    } while (0)

    LOAD_STAGE(0, 0);
    LOAD_STAGE(1, 1);
    LOAD_STAGE(2, 2);

    for (int s = 0; s < NIT; s++) {
        if (s + 3 <= NIT)      cp_wait<2>();
        else if (s + 2 == NIT) cp_wait<1>();
        else                   cp_wait<0>();
        __syncthreads();
        if (s + 3 < NIT) LOAD_STAGE(s + 3, (s + 3) & 3);

        const uint32_t sb = sbase + (s & 3) * STAGE_BYTES;
        #pragma unroll
        for (int kk = 0; kk < 4; kk++) {
            uint32_t afr[2][4];
            uint32_t bfr[4][2];
            #pragma unroll
            for (int im = 0; im < 2; im++)
                ldsm4(afr[im][0], afr[im][1], afr[im][2], afr[im][3],
                      sb + a_row_off[im] + (((kk * 2 + a_hi) ^ swz) << 4));
            #pragma unroll
            for (int j2 = 0; j2 < 2; j2++) {
                uint32_t r0, r1, r2, r3;
                ldsm4(r0, r1, r2, r3,
                      sb + b_row_off[j2] + (((kk * 2 + b_hi) ^ swz) << 4));
                bfr[j2 * 2 + 0][0] = r0; bfr[j2 * 2 + 0][1] = r1;
                bfr[j2 * 2 + 1][0] = r2; bfr[j2 * 2 + 1][1] = r3;
            }
            #pragma unroll
            for (int im = 0; im < 2; im++)
                #pragma unroll
                for (int jn = 0; jn < 4; jn++)
                    mma16816(acc[im][jn], afr[im], bfr[jn]);
        }

        // end of an a-group: fold M into T, zero M
        if ((s & 3) == 3) {
            const int a = s >> 2;
            // A0 = [1,1,1,0], A1 = [0,1,-1,-1]
            const float c0 = (a < 3) ? 1.0f : 0.0f;
            const float c1 = (a == 0) ? 0.0f : ((a == 1) ? 1.0f : -1.0f);
            const __half2 h0 = __float2half2_rn(c0);
            const __half2 h1 = __float2half2_rn(c1);
            #pragma unroll
            for (int im = 0; im < 2; im++)
                #pragma unroll
                for (int jn = 0; jn < 4; jn++) {
                    const __half2 mlo = __float22half2_rn(make_float2(acc[im][jn][0], acc[im][jn][1]));
                    const __half2 mhi = __float22half2_rn(make_float2(acc[im][jn][2], acc[im][jn][3]));
                    Tacc[0][im][jn][0] = __hfma2(h0, mlo, Tacc[0][im][jn][0]);
                    Tacc[0][im][jn][1] = __hfma2(h0, mhi, Tacc[0][im][jn][1]);
                    Tacc[1][im][jn][0] = __hfma2(h1, mlo, Tacc[1][im][jn][0]);
                    Tacc[1][im][jn][1] = __hfma2(h1, mhi, Tacc[1][im][jn][1]);
                    acc[im][jn][0] = 0.0f; acc[im][jn][1] = 0.0f;
                    acc[im][jn][2] = 0.0f; acc[im][jn][3] = 0.0f;
                }
        }
    }

    // ---- epilogue: write T0, T1 (fp16) to Tw[(b*2+p)][tile][o] ----
    const int g = lane >> 2;
    #pragma unroll
    for (int p = 0; p < 2; p++) {
        __half* tw = Tw + (size_t)(bfix * 2 + p) * TILEC;
        #pragma unroll
        for (int jn = 0; jn < 4; jn++) {
            const int n = n0 + wn + jn * 8 + (lane & 3) * 2;
            #pragma unroll
            for (int im = 0; im < 2; im++) {
                const int mrow = m0 + wm + im * 16 + g;
                *(__half2*)&tw[(size_t)mrow * NDIM + n]       = Tacc[p][im][jn][0];
                *(__half2*)&tw[(size_t)(mrow + 8) * NDIM + n] = Tacc[p][im][jn][1];
            }
        }
    }
}

// ---------------------------------------------------------------------------
// Kernel 5: output column-combine Y_pq = sum_b A_q[b] T_pb + bias, 4 o/thread
// ---------------------------------------------------------------------------
__global__ __launch_bounds__(256) void output_transform_kernel(const float* __restrict__ bias,
                                                               float* __restrict__ out)
{
    const int tid  = threadIdx.x;
    const int tile = blockIdx.x * 4 + (tid >> 6);
    const int o    = (tid & 63) * 4;

    const int b  = tile >> 10;
    const int ty = (tile >> 5) & 31;
    const int tx = tile & 31;

    float4 tv[4][2];
    #pragma unroll
    for (int bb = 0; bb < 4; bb++)
        #pragma unroll
        for (int p = 0; p < 2; p++) {
            const uint2 u = *(const uint2*)&Tw[(size_t)(bb * 2 + p) * TILEC + (size_t)tile * 256 + o];
            const float2 lo = __half22float2(*(const __half2*)&u.x);
            const float2 hi = __half22float2(*(const __half2*)&u.y);
            tv[bb][p] = make_float4(lo.x, lo.y, hi.x, hi.y);
        }

    const float4 bv = *(const float4*)&bias[o];
    float4 Y00 = f4add(f4add(f4add(tv[0][0], tv[1][0]), tv[2][0]), bv);
    float4 Y01 = f4add(f4sub(f4sub(tv[1][0], tv[2][0]), tv[3][0]), bv);
    float4 Y10 = f4add(f4add(f4add(tv[0][1], tv[1][1]), tv[2][1]), bv);
    float4 Y11 = f4add(f4sub(f4sub(tv[1][1], tv[2][1]), tv[3][1]), bv);

    const int y0 = 2 * ty, x0 = 2 * tx;
    float* obase = out + ((size_t)b * H_ * W_) * NDIM + o;
    *(float4*)&obase[((size_t)y0 * W_ + x0) * NDIM]           = Y00;
    *(float4*)&obase[((size_t)y0 * W_ + x0 + 1) * NDIM]       = Y01;
    *(float4*)&obase[((size_t)(y0 + 1) * W_ + x0) * NDIM]     = Y10;
    *(float4*)&obase[((size_t)(y0 + 1) * W_ + x0 + 1) * NDIM] = Y11;
}

// ---------------------------------------------------------------------------
extern "C" void kernel_launch(void* const* d_in, const int* in_sizes, int n_in,
                              void* d_out, int out_size)
{
    const float* grid = (const float*)d_in[0];
    const float* Wd   = (const float*)d_in[1];
    const float* Wc   = (const float*)d_in[2];
    const float* bc   = (const float*)d_in[3];
    float* out        = (float*)d_out;

    cudaFuncSetAttribute(wino_gemm_T, cudaFuncAttributeMaxDynamicSharedMemorySize, SM_TOTAL);

    fold_weights_kernel<<<128, 256>>>(Wd, Wc);
    weight_transform_kernel<<<256, 256>>>();
    input_transform_kernel<<<NTILES / 4, 256>>>(grid);
    wino_gemm_T<<<(NTILES / BM) * 2 * 4, 256, SM_TOTAL>>>();
    output_transform_kernel<<<NTILES / 4, 256>>>(bc, out);
}

// round 10
// speedup vs baseline: 1.0176x; 1.0176x over previous
#include <cuda_runtime.h>
#include <cuda_fp16.h>
#include <cstdint>
#include <cstddef>

#define B_   16
#define H_   64
#define W_   64
#define C_   256
#define NDIM 256
#define NTILES 16384                 // 16 * 32 * 32 (2x2 output tiles)
#define TILEC  ((size_t)NTILES * 256)

// GEMM tiling (K = 256 per Winograd point; CTA loops a=0..3 for fixed b)
#define KD2  256
#define BM 64
#define BN 128
#define BK 64
#define NIT 16                       // 4 a-values x 4 BK-chunks
#define NSTAGE 3
#define A_BYTES (BM * 128)
#define B_BYTES (BN * 128)
#define STAGE_BYTES (A_BYTES + B_BYTES)   // 24 KB
#define SM_TOTAL (NSTAGE * STAGE_BYTES)   // 72 KB (2 CTAs/SM = 144 KB)

__device__ __align__(16) float  Mf[(size_t)C_ * 256 * 8];          // [c][o][d] 2 MB
__device__ __align__(16) __half U_buf[(size_t)16 * 256 * 256];     // [k][o][c] 2 MB
__device__ __align__(16) __half V_buf[(size_t)16 * TILEC];         // [k][tile][c] 128 MB
__device__ __align__(16) __half Tw[(size_t)8 * TILEC];             // [b*2+p][tile][o] 64 MB

// ---------------------------------------------------------------------------
__device__ __forceinline__ uint32_t smem_u32(const void* p) {
    uint32_t a;
    asm("{ .reg .u64 t; cvta.to.shared.u64 t, %1; cvt.u32.u64 %0, t; }" : "=r"(a) : "l"(p));
    return a;
}
__device__ __forceinline__ void cp_async16(uint32_t dst, const void* src) {
    asm volatile("cp.async.cg.shared.global [%0], [%1], 16;" :: "r"(dst), "l"(src));
}
__device__ __forceinline__ void cp_commit() {
    asm volatile("cp.async.commit_group;" ::: "memory");
}
template<int N> __device__ __forceinline__ void cp_wait() {
    asm volatile("cp.async.wait_group %0;" :: "n"(N) : "memory");
}
__device__ __forceinline__ void ldsm4(uint32_t& r0, uint32_t& r1, uint32_t& r2, uint32_t& r3,
                                      uint32_t addr) {
    asm volatile("ldmatrix.sync.aligned.m8n8.x4.shared.b16 {%0,%1,%2,%3}, [%4];"
                 : "=r"(r0), "=r"(r1), "=r"(r2), "=r"(r3) : "r"(addr));
}
__device__ __forceinline__ void mma16816(float* d, const uint32_t* a, const uint32_t* b) {
    asm volatile(
        "mma.sync.aligned.m16n8k16.row.col.f32.f16.f16.f32 "
        "{%0,%1,%2,%3}, {%4,%5,%6,%7}, {%8,%9}, {%0,%1,%2,%3};\n"
        : "+f"(d[0]), "+f"(d[1]), "+f"(d[2]), "+f"(d[3])
        : "r"(a[0]), "r"(a[1]), "r"(a[2]), "r"(a[3]), "r"(b[0]), "r"(b[1]));
}
__device__ __forceinline__ float4 f4add(float4 a, float4 b) {
    return make_float4(a.x + b.x, a.y + b.y, a.z + b.z, a.w + b.w);
}
__device__ __forceinline__ float4 f4sub(float4 a, float4 b) {
    return make_float4(a.x - b.x, a.y - b.y, a.z - b.z, a.w - b.w);
}

// ---------------------------------------------------------------------------
// Kernel 1: fold weights -> Mf[c][o][d] (fp32)
// ---------------------------------------------------------------------------
__global__ void fold_weights_kernel(const float* __restrict__ Wd,
                                    const float* __restrict__ Wc)
{
    const int bid = blockIdx.x;
    const int d  = bid >> 4;
    const int ct = (bid >> 2) & 3;
    const int et = bid & 3;

    __shared__ float WdS[64][33];
    __shared__ float WcS[64][33];

    const int t  = threadIdx.x;
    const int tx = t & 15;
    const int ty = t >> 4;

    float acc[4][4];
    #pragma unroll
    for (int i = 0; i < 4; i++)
        #pragma unroll
        for (int j = 0; j < 4; j++) acc[i][j] = 0.0f;

    const float* WdBase = Wd + (size_t)d * C_ * C_ + (size_t)(ct * 64) * C_;
    const float* WcBase = Wc + (size_t)(et * 64) * (8 * C_) + d * C_;

    const int ci  = t >> 2;
    const int kk0 = (t & 3) * 8;

    for (int k0 = 0; k0 < C_; k0 += 32) {
        const float* srcA = WdBase + (size_t)ci * C_        + k0 + kk0;
        const float* srcB = WcBase + (size_t)ci * (8 * C_)  + k0 + kk0;
        #pragma unroll
        for (int u = 0; u < 8; u++) WdS[ci][kk0 + u] = srcA[u];
        #pragma unroll
        for (int u = 0; u < 8; u++) WcS[ci][kk0 + u] = srcB[u];
        __syncthreads();
        #pragma unroll
        for (int kk = 0; kk < 32; kk++) {
            float a[4], bb[4];
            #pragma unroll
            for (int i = 0; i < 4; i++) a[i]  = WdS[ty * 4 + i][kk];
            #pragma unroll
            for (int j = 0; j < 4; j++) bb[j] = WcS[tx * 4 + j][kk];
            #pragma unroll
            for (int i = 0; i < 4; i++)
                #pragma unroll
                for (int j = 0; j < 4; j++) acc[i][j] += a[i] * bb[j];
        }
        __syncthreads();
    }
    #pragma unroll
    for (int i = 0; i < 4; i++) {
        const int c = ct * 64 + ty * 4 + i;
        #pragma unroll
        for (int j = 0; j < 4; j++) {
            const int o = et * 64 + tx * 4 + j;
            Mf[((size_t)c * 256 + o) * 8 + d] = acc[i][j];
        }
    }
}

// ---------------------------------------------------------------------------
// Kernel 2: weight transform U_k = G K G^T  (k = a*4+b), fp16 [k][o][c]
// ---------------------------------------------------------------------------
__global__ __launch_bounds__(256) void weight_transform_kernel()
{
    const int o = blockIdx.x;
    const int c = threadIdx.x;

    const float* mp = &Mf[((size_t)c * 256 + o) * 8];
    float m[8];
    const float4 f0 = *(const float4*)(mp);
    const float4 f1 = *(const float4*)(mp + 4);
    m[0]=f0.x; m[1]=f0.y; m[2]=f0.z; m[3]=f0.w;
    m[4]=f1.x; m[5]=f1.y; m[6]=f1.z; m[7]=f1.w;

    float K[3][3];
    K[0][0]=m[3]; K[0][1]=m[4]; K[0][2]=m[5];
    K[1][0]=m[2]; K[1][1]=0.f;  K[1][2]=m[6];
    K[2][0]=m[1]; K[2][1]=m[0]; K[2][2]=m[7];

    float T[4][3];
    #pragma unroll
    for (int j = 0; j < 3; j++) {
        T[0][j] = K[0][j];
        T[1][j] = 0.5f * (K[0][j] + K[1][j] + K[2][j]);
        T[2][j] = 0.5f * (K[0][j] - K[1][j] + K[2][j]);
        T[3][j] = K[2][j];
    }
    #pragma unroll
    for (int a = 0; a < 4; a++) {
        float U0 = T[a][0];
        float U1 = 0.5f * (T[a][0] + T[a][1] + T[a][2]);
        float U2 = 0.5f * (T[a][0] - T[a][1] + T[a][2]);
        float U3 = T[a][2];
        U_buf[(size_t)(a * 4 + 0) * 65536 + o * 256 + c] = __float2half(U0);
        U_buf[(size_t)(a * 4 + 1) * 65536 + o * 256 + c] = __float2half(U1);
        U_buf[(size_t)(a * 4 + 2) * 65536 + o * 256 + c] = __float2half(U2);
        U_buf[(size_t)(a * 4 + 3) * 65536 + o * 256 + c] = __float2half(U3);
    }
}

// ---------------------------------------------------------------------------
// Kernel 3: FUSED pad + input transform (fp32 grid -> fp16 V), float4/thread
// ---------------------------------------------------------------------------
__global__ __launch_bounds__(256) void input_transform_kernel(const float* __restrict__ g)
{
    const int tid  = threadIdx.x;
    const int tile = blockIdx.x * 4 + (tid >> 6);
    const int c    = (tid & 63) * 4;

    const int b  = tile >> 10;
    const int ty = (tile >> 5) & 31;
    const int tx = tile & 31;

    const int gy0 = 2 * ty - 1;
    const int gx0 = 2 * tx - 1;
    const float* gbase = g + ((size_t)b * H_ * W_) * C_ + c;

    float4 d[4][4];
    #pragma unroll
    for (int i = 0; i < 4; i++) {
        const int gy = gy0 + i;
        const bool vy = (gy >= 0) && (gy < H_);
        #pragma unroll
        for (int j = 0; j < 4; j++) {
            const int gx = gx0 + j;
            if (vy && gx >= 0 && gx < W_)
                d[i][j] = *(const float4*)(gbase + ((size_t)gy * W_ + gx) * C_);
            else
                d[i][j] = make_float4(0.0f, 0.0f, 0.0f, 0.0f);
        }
    }

    float4 tr[4][4];
    #pragma unroll
    for (int j = 0; j < 4; j++) {
        tr[0][j] = f4sub(d[0][j], d[2][j]);
        tr[1][j] = f4add(d[1][j], d[2][j]);
        tr[2][j] = f4sub(d[2][j], d[1][j]);
        tr[3][j] = f4sub(d[1][j], d[3][j]);
    }
    #pragma unroll
    for (int a = 0; a < 4; a++) {
        float4 V[4];
        V[0] = f4sub(tr[a][0], tr[a][2]);
        V[1] = f4add(tr[a][1], tr[a][2]);
        V[2] = f4sub(tr[a][2], tr[a][1]);
        V[3] = f4sub(tr[a][1], tr[a][3]);
        #pragma unroll
        for (int bb = 0; bb < 4; bb++) {
            __half2 lo = __floats2half2_rn(V[bb].x, V[bb].y);
            __half2 hi = __floats2half2_rn(V[bb].z, V[bb].w);
            uint2 u;
            u.x = *(uint32_t*)&lo;
            u.y = *(uint32_t*)&hi;
            *(uint2*)&V_buf[(size_t)(a * 4 + bb) * TILEC + (size_t)tile * 256 + c] = u;
        }
    }
}

// ---------------------------------------------------------------------------
// Kernel 4: GEMM with fused Winograd row-combine (3-stage cp.async — the
// measured-best schedule from R8).
// CTA = (m-block, n-half, b). Loops a=0..3: M_a = V_{a*4+b} @ U_{a*4+b}^T,
// folds into T_p = sum_a A_p[a] * M_a (fp16x2 accumulators), writes Tw.
// ---------------------------------------------------------------------------
__global__ __launch_bounds__(256, 2) void wino_gemm_T(void)
{
    extern __shared__ __align__(1024) char smem[];
    const uint32_t sbase = smem_u32(smem);

    const int t    = threadIdx.x;
    const int warp = t >> 5, lane = t & 31;
    const int bx   = blockIdx.x;
    const int n0   = (bx & 1) * BN;
    const int bfix = (bx >> 1) & 3;
    const int m0   = (bx >> 3) * BM;

    // ---- producer setup ----
    const int arow   = t >> 2;
    const int acpair = (t & 3) * 2;
    const int brow = t >> 1;
    const int bc0  = (t & 1) * 4;

    const __half* a_base = V_buf + (size_t)bfix * TILEC + (size_t)(m0 + arow) * KD2 + acpair * 8;
    const __half* b_base = U_buf + (size_t)bfix * 65536 + (size_t)(n0 + brow) * KD2 + bc0 * 8;

    uint32_t a_dst[2], b_dst[4];
    #pragma unroll
    for (int j = 0; j < 2; j++)
        a_dst[j] = (uint32_t)(arow * 128 + (((acpair + j) ^ (arow & 7)) << 4));
    #pragma unroll
    for (int j = 0; j < 4; j++)
        b_dst[j] = (uint32_t)(A_BYTES + brow * 128 + (((bc0 + j) ^ (brow & 7)) << 4));

    // ---- consumer setup: warp tile 32x32 ----
    const int wm = (warp >> 2) * 32;
    const int wn = (warp & 3) * 32;
    const int swz  = lane & 7;
    const int a_hi = lane >> 4;
    const int b_hi = (lane >> 3) & 1;

    uint32_t a_row_off[2], b_row_off[2];
    #pragma unroll
    for (int im = 0; im < 2; im++)
        a_row_off[im] = (uint32_t)((wm + im * 16 + (lane & 15)) * 128);
    #pragma unroll
    for (int j2 = 0; j2 < 2; j2++)
        b_row_off[j2] = (uint32_t)(A_BYTES +
            (wn + j2 * 16 + ((lane >> 4) << 3) + (lane & 7)) * 128);

    float acc[2][4][4];
    #pragma unroll
    for (int i = 0; i < 2; i++)
        #pragma unroll
        for (int j = 0; j < 4; j++)
            #pragma unroll
            for (int r = 0; r < 4; r++) acc[i][j][r] = 0.0f;

    __half2 Tacc[2][2][4][2];
    #pragma unroll
    for (int p = 0; p < 2; p++)
        #pragma unroll
        for (int i = 0; i < 2; i++)
            #pragma unroll
            for (int j = 0; j < 4; j++) {
                Tacc[p][i][j][0] = __half2half2(__float2half(0.0f));
                Tacc[p][i][j][1] = __half2half2(__float2half(0.0f));
            }

    #define LOAD_STAGE(I, S)                                                       \
    do {                                                                           \
        const int a_  = (I) >> 2;                                                  \
        const int kt_ = (I) & 3;                                                   \
        const __half* asrc = a_base + (size_t)(a_ * 4) * TILEC + kt_ * 64;         \
        const __half* bsrc = b_base + (size_t)(a_ * 4) * 65536 + kt_ * 64;         \
        const uint32_t sb  = sbase + (S) * STAGE_BYTES;                            \
        _Pragma("unroll")                                                          \
        for (int j = 0; j < 2; j++) cp_async16(sb + a_dst[j], asrc + j * 8);       \
        _Pragma("unroll")                                                          \
        for (int j = 0; j < 4; j++) cp_async16(sb + b_dst[j], bsrc + j * 8);       \
        cp_commit();                                                               \
    } while (0)

    LOAD_STAGE(0, 0);
    LOAD_STAGE(1, 1);

    for (int s = 0; s < NIT; s++) {
        if (s + 2 < NIT) cp_wait<1>(); else cp_wait<0>();
        __syncthreads();
        if (s + 2 < NIT) LOAD_STAGE(s + 2, (s + 2) % NSTAGE);

        const uint32_t sb = sbase + (s % NSTAGE) * STAGE_BYTES;
        #pragma unroll
        for (int kk = 0; kk < 4; kk++) {
            uint32_t afr[2][4];
            uint32_t bfr[4][2];
            #pragma unroll
            for (int im = 0; im < 2; im++)
                ldsm4(afr[im][0], afr[im][1], afr[im][2], afr[im][3],
                      sb + a_row_off[im] + (((kk * 2 + a_hi) ^ swz) << 4));
            #pragma unroll
            for (int j2 = 0; j2 < 2; j2++) {
                uint32_t r0, r1, r2, r3;
                ldsm4(r0, r1, r2, r3,
                      sb + b_row_off[j2] + (((kk * 2 + b_hi) ^ swz) << 4));
                bfr[j2 * 2 + 0][0] = r0; bfr[j2 * 2 + 0][1] = r1;
                bfr[j2 * 2 + 1][0] = r2; bfr[j2 * 2 + 1][1] = r3;
            }
            #pragma unroll
            for (int im = 0; im < 2; im++)
                #pragma unroll
                for (int jn = 0; jn < 4; jn++)
                    mma16816(acc[im][jn], afr[im], bfr[jn]);
        }

        // end of an a-group: fold M into T, zero M
        if ((s & 3) == 3) {
            const int a = s >> 2;
            // A0 = [1,1,1,0], A1 = [0,1,-1,-1]
            const float c0 = (a < 3) ? 1.0f : 0.0f;
            const float c1 = (a == 0) ? 0.0f : ((a == 1) ? 1.0f : -1.0f);
            const __half2 h0 = __float2half2_rn(c0);
            const __half2 h1 = __float2half2_rn(c1);
            #pragma unroll
            for (int im = 0; im < 2; im++)
                #pragma unroll
                for (int jn = 0; jn < 4; jn++) {
                    const __half2 mlo = __float22half2_rn(make_float2(acc[im][jn][0], acc[im][jn][1]));
                    const __half2 mhi = __float22half2_rn(make_float2(acc[im][jn][2], acc[im][jn][3]));
                    Tacc[0][im][jn][0] = __hfma2(h0, mlo, Tacc[0][im][jn][0]);
                    Tacc[0][im][jn][1] = __hfma2(h0, mhi, Tacc[0][im][jn][1]);
                    Tacc[1][im][jn][0] = __hfma2(h1, mlo, Tacc[1][im][jn][0]);
                    Tacc[1][im][jn][1] = __hfma2(h1, mhi, Tacc[1][im][jn][1]);
                    acc[im][jn][0] = 0.0f; acc[im][jn][1] = 0.0f;
                    acc[im][jn][2] = 0.0f; acc[im][jn][3] = 0.0f;
                }
        }
    }

    // ---- epilogue: write T0, T1 (fp16) to Tw[(b*2+p)][tile][o] ----
    const int g = lane >> 2;
    #pragma unroll
    for (int p = 0; p < 2; p++) {
        __half* tw = Tw + (size_t)(bfix * 2 + p) * TILEC;
        #pragma unroll
        for (int jn = 0; jn < 4; jn++) {
            const int n = n0 + wn + jn * 8 + (lane & 3) * 2;
            #pragma unroll
            for (int im = 0; im < 2; im++) {
                const int mrow = m0 + wm + im * 16 + g;
                *(__half2*)&tw[(size_t)mrow * NDIM + n]       = Tacc[p][im][jn][0];
                *(__half2*)&tw[(size_t)(mrow + 8) * NDIM + n] = Tacc[p][im][jn][1];
            }
        }
    }
}

// ---------------------------------------------------------------------------
// Kernel 5: output column-combine Y_pq = sum_b A_q[b] T_pb + bias, 4 o/thread
// ---------------------------------------------------------------------------
__global__ __launch_bounds__(256) void output_transform_kernel(const float* __restrict__ bias,
                                                               float* __restrict__ out)
{
    const int tid  = threadIdx.x;
    const int tile = blockIdx.x * 4 + (tid >> 6);
    const int o    = (tid & 63) * 4;

    const int b  = tile >> 10;
    const int ty = (tile >> 5) & 31;
    const int tx = tile & 31;

    float4 tv[4][2];
    #pragma unroll
    for (int bb = 0; bb < 4; bb++)
        #pragma unroll
        for (int p = 0; p < 2; p++) {
            const uint2 u = *(const uint2*)&Tw[(size_t)(bb * 2 + p) * TILEC + (size_t)tile * 256 + o];
            const float2 lo = __half22float2(*(const __half2*)&u.x);
            const float2 hi = __half22float2(*(const __half2*)&u.y);
            tv[bb][p] = make_float4(lo.x, lo.y, hi.x, hi.y);
        }

    const float4 bv = *(const float4*)&bias[o];
    float4 Y00 = f4add(f4add(f4add(tv[0][0], tv[1][0]), tv[2][0]), bv);
    float4 Y01 = f4add(f4sub(f4sub(tv[1][0], tv[2][0]), tv[3][0]), bv);
    float4 Y10 = f4add(f4add(f4add(tv[0][1], tv[1][1]), tv[2][1]), bv);
    float4 Y11 = f4add(f4sub(f4sub(tv[1][1], tv[2][1]), tv[3][1]), bv);

    const int y0 = 2 * ty, x0 = 2 * tx;
    float* obase = out + ((size_t)b * H_ * W_) * NDIM + o;
    *(float4*)&obase[((size_t)y0 * W_ + x0) * NDIM]           = Y00;
    *(float4*)&obase[((size_t)y0 * W_ + x0 + 1) * NDIM]       = Y01;
    *(float4*)&obase[((size_t)(y0 + 1) * W_ + x0) * NDIM]     = Y10;
    *(float4*)&obase[((size_t)(y0 + 1) * W_ + x0 + 1) * NDIM] = Y11;
}

// ---------------------------------------------------------------------------
extern "C" void kernel_launch(void* const* d_in, const int* in_sizes, int n_in,
                              void* d_out, int out_size)
{
    const float* grid = (const float*)d_in[0];
    const float* Wd   = (const float*)d_in[1];
    const float* Wc   = (const float*)d_in[2];
    const float* bc   = (const float*)d_in[3];
    float* out        = (float*)d_out;

    cudaFuncSetAttribute(wino_gemm_T, cudaFuncAttributeMaxDynamicSharedMemorySize, SM_TOTAL);

    fold_weights_kernel<<<128, 256>>>(Wd, Wc);
    weight_transform_kernel<<<256, 256>>>();
    input_transform_kernel<<<NTILES / 4, 256>>>(grid);
    wino_gemm_T<<<(NTILES / BM) * 2 * 4, 256, SM_TOTAL>>>();
    output_transform_kernel<<<NTILES / 4, 256>>>(bc, out);
}

// round 11
// speedup vs baseline: 1.0668x; 1.0484x over previous
#include <cuda_runtime.h>
#include <cuda_fp16.h>
#include <cstdint>
#include <cstddef>

#define B_   16
#define H_   64
#define W_   64
#define C_   256
#define NDIM 256
#define NTILES 16384                 // 16 * 32 * 32 (2x2 output tiles)
#define TILEC  ((size_t)NTILES * 256)

// GEMM tiling (K = 256 per Winograd point; CTA loops a=0..3 for fixed b)
#define KD2  256
#define BM 64
#define BN 128
#define BK 64
#define NIT 16                       // 4 a-values x 4 BK-chunks
#define NSTAGE 3
#define A_BYTES (BM * 128)
#define B_BYTES (BN * 128)
#define STAGE_BYTES (A_BYTES + B_BYTES)   // 24 KB
#define SM_TOTAL (NSTAGE * STAGE_BYTES)   // 72 KB (2 CTAs/SM = 144 KB)

__device__ __align__(16) float  Mf[(size_t)C_ * 256 * 8];          // [c][o][d] 2 MB
__device__ __align__(16) __half U_buf[(size_t)16 * 256 * 256];     // [k][o][c] 2 MB
__device__ __align__(16) __half V_buf[(size_t)16 * TILEC];         // [k][tile][c] 128 MB
__device__ __align__(16) __half Tw[(size_t)8 * TILEC];             // [b*2+p][tile][o] 64 MB

// ---------------------------------------------------------------------------
__device__ __forceinline__ uint32_t smem_u32(const void* p) {
    uint32_t a;
    asm("{ .reg .u64 t; cvta.to.shared.u64 t, %1; cvt.u32.u64 %0, t; }" : "=r"(a) : "l"(p));
    return a;
}
__device__ __forceinline__ void cp_async16(uint32_t dst, const void* src) {
    asm volatile("cp.async.cg.shared.global [%0], [%1], 16;" :: "r"(dst), "l"(src));
}
__device__ __forceinline__ void cp_commit() {
    asm volatile("cp.async.commit_group;" ::: "memory");
}
template<int N> __device__ __forceinline__ void cp_wait() {
    asm volatile("cp.async.wait_group %0;" :: "n"(N) : "memory");
}
__device__ __forceinline__ void ldsm4(uint32_t& r0, uint32_t& r1, uint32_t& r2, uint32_t& r3,
                                      uint32_t addr) {
    asm volatile("ldmatrix.sync.aligned.m8n8.x4.shared.b16 {%0,%1,%2,%3}, [%4];"
                 : "=r"(r0), "=r"(r1), "=r"(r2), "=r"(r3) : "r"(addr));
}
__device__ __forceinline__ void mma16816(float* d, const uint32_t* a, const uint32_t* b) {
    asm volatile(
        "mma.sync.aligned.m16n8k16.row.col.f32.f16.f16.f32 "
        "{%0,%1,%2,%3}, {%4,%5,%6,%7}, {%8,%9}, {%0,%1,%2,%3};\n"
        : "+f"(d[0]), "+f"(d[1]), "+f"(d[2]), "+f"(d[3])
        : "r"(a[0]), "r"(a[1]), "r"(a[2]), "r"(a[3]), "r"(b[0]), "r"(b[1]));
}
__device__ __forceinline__ float4 f4add(float4 a, float4 b) {
    return make_float4(a.x + b.x, a.y + b.y, a.z + b.z, a.w + b.w);
}
__device__ __forceinline__ float4 f4sub(float4 a, float4 b) {
    return make_float4(a.x - b.x, a.y - b.y, a.z - b.z, a.w - b.w);
}

// ---------------------------------------------------------------------------
// Kernel 1: fold weights -> Mf[c][o][d] (fp32)
// ---------------------------------------------------------------------------
__global__ void fold_weights_kernel(const float* __restrict__ Wd,
                                    const float* __restrict__ Wc)
{
    const int bid = blockIdx.x;
    const int d  = bid >> 4;
    const int ct = (bid >> 2) & 3;
    const int et = bid & 3;

    __shared__ float WdS[64][33];
    __shared__ float WcS[64][33];

    const int t  = threadIdx.x;
    const int tx = t & 15;
    const int ty = t >> 4;

    float acc[4][4];
    #pragma unroll
    for (int i = 0; i < 4; i++)
        #pragma unroll
        for (int j = 0; j < 4; j++) acc[i][j] = 0.0f;

    const float* WdBase = Wd + (size_t)d * C_ * C_ + (size_t)(ct * 64) * C_;
    const float* WcBase = Wc + (size_t)(et * 64) * (8 * C_) + d * C_;

    const int ci  = t >> 2;
    const int kk0 = (t & 3) * 8;

    for (int k0 = 0; k0 < C_; k0 += 32) {
        const float* srcA = WdBase + (size_t)ci * C_        + k0 + kk0;
        const float* srcB = WcBase + (size_t)ci * (8 * C_)  + k0 + kk0;
        #pragma unroll
        for (int u = 0; u < 8; u++) WdS[ci][kk0 + u] = srcA[u];
        #pragma unroll
        for (int u = 0; u < 8; u++) WcS[ci][kk0 + u] = srcB[u];
        __syncthreads();
        #pragma unroll
        for (int kk = 0; kk < 32; kk++) {
            float a[4], bb[4];
            #pragma unroll
            for (int i = 0; i < 4; i++) a[i]  = WdS[ty * 4 + i][kk];
            #pragma unroll
            for (int j = 0; j < 4; j++) bb[j] = WcS[tx * 4 + j][kk];
            #pragma unroll
            for (int i = 0; i < 4; i++)
                #pragma unroll
                for (int j = 0; j < 4; j++) acc[i][j] += a[i] * bb[j];
        }
        __syncthreads();
    }
    #pragma unroll
    for (int i = 0; i < 4; i++) {
        const int c = ct * 64 + ty * 4 + i;
        #pragma unroll
        for (int j = 0; j < 4; j++) {
            const int o = et * 64 + tx * 4 + j;
            Mf[((size_t)c * 256 + o) * 8 + d] = acc[i][j];
        }
    }
}

// ---------------------------------------------------------------------------
// Kernel 2: weight transform U_k = G K G^T  (k = a*4+b), fp16 [k][o][c]
// ---------------------------------------------------------------------------
__global__ __launch_bounds__(256) void weight_transform_kernel()
{
    const int o = blockIdx.x;
    const int c = threadIdx.x;

    const float* mp = &Mf[((size_t)c * 256 + o) * 8];
    float m[8];
    const float4 f0 = *(const float4*)(mp);
    const float4 f1 = *(const float4*)(mp + 4);
    m[0]=f0.x; m[1]=f0.y; m[2]=f0.z; m[3]=f0.w;
    m[4]=f1.x; m[5]=f1.y; m[6]=f1.z; m[7]=f1.w;

    float K[3][3];
    K[0][0]=m[3]; K[0][1]=m[4]; K[0][2]=m[5];
    K[1][0]=m[2]; K[1][1]=0.f;  K[1][2]=m[6];
    K[2][0]=m[1]; K[2][1]=m[0]; K[2][2]=m[7];

    float T[4][3];
    #pragma unroll
    for (int j = 0; j < 3; j++) {
        T[0][j] = K[0][j];
        T[1][j] = 0.5f * (K[0][j] + K[1][j] + K[2][j]);
        T[2][j] = 0.5f * (K[0][j] - K[1][j] + K[2][j]);
        T[3][j] = K[2][j];
    }
    #pragma unroll
    for (int a = 0; a < 4; a++) {
        float U0 = T[a][0];
        float U1 = 0.5f * (T[a][0] + T[a][1] + T[a][2]);
        float U2 = 0.5f * (T[a][0] - T[a][1] + T[a][2]);
        float U3 = T[a][2];
        U_buf[(size_t)(a * 4 + 0) * 65536 + o * 256 + c] = __float2half(U0);
        U_buf[(size_t)(a * 4 + 1) * 65536 + o * 256 + c] = __float2half(U1);
        U_buf[(size_t)(a * 4 + 2) * 65536 + o * 256 + c] = __float2half(U2);
        U_buf[(size_t)(a * 4 + 3) * 65536 + o * 256 + c] = __float2half(U3);
    }
}

// ---------------------------------------------------------------------------
// Kernel 3: FUSED pad + input transform (fp32 grid -> fp16 V), float4/thread
// ---------------------------------------------------------------------------
__global__ __launch_bounds__(256) void input_transform_kernel(const float* __restrict__ g)
{
    const int tid  = threadIdx.x;
    const int tile = blockIdx.x * 4 + (tid >> 6);
    const int c    = (tid & 63) * 4;

    const int b  = tile >> 10;
    const int ty = (tile >> 5) & 31;
    const int tx = tile & 31;

    const int gy0 = 2 * ty - 1;
    const int gx0 = 2 * tx - 1;
    const float* gbase = g + ((size_t)b * H_ * W_) * C_ + c;

    float4 d[4][4];
    #pragma unroll
    for (int i = 0; i < 4; i++) {
        const int gy = gy0 + i;
        const bool vy = (gy >= 0) && (gy < H_);
        #pragma unroll
        for (int j = 0; j < 4; j++) {
            const int gx = gx0 + j;
            if (vy && gx >= 0 && gx < W_)
                d[i][j] = *(const float4*)(gbase + ((size_t)gy * W_ + gx) * C_);
            else
                d[i][j] = make_float4(0.0f, 0.0f, 0.0f, 0.0f);
        }
    }

    float4 tr[4][4];
    #pragma unroll
    for (int j = 0; j < 4; j++) {
        tr[0][j] = f4sub(d[0][j], d[2][j]);
        tr[1][j] = f4add(d[1][j], d[2][j]);
        tr[2][j] = f4sub(d[2][j], d[1][j]);
        tr[3][j] = f4sub(d[1][j], d[3][j]);
    }
    #pragma unroll
    for (int a = 0; a < 4; a++) {
        float4 V[4];
        V[0] = f4sub(tr[a][0], tr[a][2]);
        V[1] = f4add(tr[a][1], tr[a][2]);
        V[2] = f4sub(tr[a][2], tr[a][1]);
        V[3] = f4sub(tr[a][1], tr[a][3]);
        #pragma unroll
        for (int bb = 0; bb < 4; bb++) {
            __half2 lo = __floats2half2_rn(V[bb].x, V[bb].y);
            __half2 hi = __floats2half2_rn(V[bb].z, V[bb].w);
            uint2 u;
            u.x = *(uint32_t*)&lo;
            u.y = *(uint32_t*)&hi;
            *(uint2*)&V_buf[(size_t)(a * 4 + bb) * TILEC + (size_t)tile * 256 + c] = u;
        }
    }
}

// ---------------------------------------------------------------------------
// Kernel 4: GEMM with fused Winograd row-combine (3-stage cp.async — the
// measured-best schedule). Fold specialized per a-value with compile-time
// coefficient structure (bit-identical arithmetic to the hfma2 version).
// ---------------------------------------------------------------------------
__global__ __launch_bounds__(256, 2) void wino_gemm_T(void)
{
    extern __shared__ __align__(1024) char smem[];
    const uint32_t sbase = smem_u32(smem);

    const int t    = threadIdx.x;
    const int warp = t >> 5, lane = t & 31;
    const int bx   = blockIdx.x;
    const int n0   = (bx & 1) * BN;
    const int bfix = (bx >> 1) & 3;
    const int m0   = (bx >> 3) * BM;

    // ---- producer setup ----
    const int arow   = t >> 2;
    const int acpair = (t & 3) * 2;
    const int brow = t >> 1;
    const int bc0  = (t & 1) * 4;

    const __half* a_base = V_buf + (size_t)bfix * TILEC + (size_t)(m0 + arow) * KD2 + acpair * 8;
    const __half* b_base = U_buf + (size_t)bfix * 65536 + (size_t)(n0 + brow) * KD2 + bc0 * 8;

    uint32_t a_dst[2], b_dst[4];
    #pragma unroll
    for (int j = 0; j < 2; j++)
        a_dst[j] = (uint32_t)(arow * 128 + (((acpair + j) ^ (arow & 7)) << 4));
    #pragma unroll
    for (int j = 0; j < 4; j++)
        b_dst[j] = (uint32_t)(A_BYTES + brow * 128 + (((bc0 + j) ^ (brow & 7)) << 4));

    // ---- consumer setup: warp tile 32x32 ----
    const int wm = (warp >> 2) * 32;
    const int wn = (warp & 3) * 32;
    const int swz  = lane & 7;
    const int a_hi = lane >> 4;
    const int b_hi = (lane >> 3) & 1;

    uint32_t a_row_off[2], b_row_off[2];
    #pragma unroll
    for (int im = 0; im < 2; im++)
        a_row_off[im] = (uint32_t)((wm + im * 16 + (lane & 15)) * 128);
    #pragma unroll
    for (int j2 = 0; j2 < 2; j2++)
        b_row_off[j2] = (uint32_t)(A_BYTES +
            (wn + j2 * 16 + ((lane >> 4) << 3) + (lane & 7)) * 128);

    float acc[2][4][4];
    #pragma unroll
    for (int i = 0; i < 2; i++)
        #pragma unroll
        for (int j = 0; j < 4; j++)
            #pragma unroll
            for (int r = 0; r < 4; r++) acc[i][j][r] = 0.0f;

    __half2 Tacc[2][2][4][2];
    #pragma unroll
    for (int p = 0; p < 2; p++)
        #pragma unroll
        for (int i = 0; i < 2; i++)
            #pragma unroll
            for (int j = 0; j < 4; j++) {
                Tacc[p][i][j][0] = __half2half2(__float2half(0.0f));
                Tacc[p][i][j][1] = __half2half2(__float2half(0.0f));
            }

    #define LOAD_STAGE(I, S)                                                       \
    do {                                                                           \
        const int a_  = (I) >> 2;                                                  \
        const int kt_ = (I) & 3;                                                   \
        const __half* asrc = a_base + (size_t)(a_ * 4) * TILEC + kt_ * 64;         \
        const __half* bsrc = b_base + (size_t)(a_ * 4) * 65536 + kt_ * 64;         \
        const uint32_t sb  = sbase + (S) * STAGE_BYTES;                            \
        _Pragma("unroll")                                                          \
        for (int j = 0; j < 2; j++) cp_async16(sb + a_dst[j], asrc + j * 8);       \
        _Pragma("unroll")                                                          \
        for (int j = 0; j < 4; j++) cp_async16(sb + b_dst[j], bsrc + j * 8);       \
        cp_commit();                                                               \
    } while (0)

    LOAD_STAGE(0, 0);
    LOAD_STAGE(1, 1);

    for (int s = 0; s < NIT; s++) {
        if (s + 2 < NIT) cp_wait<1>(); else cp_wait<0>();
        __syncthreads();
        if (s + 2 < NIT) LOAD_STAGE(s + 2, (s + 2) % NSTAGE);

        const uint32_t sb = sbase + (s % NSTAGE) * STAGE_BYTES;
        #pragma unroll
        for (int kk = 0; kk < 4; kk++) {
            uint32_t afr[2][4];
            uint32_t bfr[4][2];
            #pragma unroll
            for (int im = 0; im < 2; im++)
                ldsm4(afr[im][0], afr[im][1], afr[im][2], afr[im][3],
                      sb + a_row_off[im] + (((kk * 2 + a_hi) ^ swz) << 4));
            #pragma unroll
            for (int j2 = 0; j2 < 2; j2++) {
                uint32_t r0, r1, r2, r3;
                ldsm4(r0, r1, r2, r3,
                      sb + b_row_off[j2] + (((kk * 2 + b_hi) ^ swz) << 4));
                bfr[j2 * 2 + 0][0] = r0; bfr[j2 * 2 + 0][1] = r1;
                bfr[j2 * 2 + 1][0] = r2; bfr[j2 * 2 + 1][1] = r3;
            }
            #pragma unroll
            for (int im = 0; im < 2; im++)
                #pragma unroll
                for (int jn = 0; jn < 4; jn++)
                    mma16816(acc[im][jn], afr[im], bfr[jn]);
        }

        // end of an a-group: fold M into T with specialized coefficients
        // A0 = [1,1,1,0], A1 = [0,1,-1,-1]  (bit-identical to hfma2 ±1/0 form)
        if ((s & 3) == 3) {
            const int a = s >> 2;
            #pragma unroll
            for (int im = 0; im < 2; im++)
                #pragma unroll
                for (int jn = 0; jn < 4; jn++) {
                    const __half2 mlo = __float22half2_rn(make_float2(acc[im][jn][0], acc[im][jn][1]));
                    const __half2 mhi = __float22half2_rn(make_float2(acc[im][jn][2], acc[im][jn][3]));
                    if (a == 0) {
                        Tacc[0][im][jn][0] = mlo;
                        Tacc[0][im][jn][1] = mhi;
                    } else if (a == 1) {
                        Tacc[0][im][jn][0] = __hadd2(Tacc[0][im][jn][0], mlo);
                        Tacc[0][im][jn][1] = __hadd2(Tacc[0][im][jn][1], mhi);
                        Tacc[1][im][jn][0] = mlo;
                        Tacc[1][im][jn][1] = mhi;
                    } else if (a == 2) {
                        Tacc[0][im][jn][0] = __hadd2(Tacc[0][im][jn][0], mlo);
                        Tacc[0][im][jn][1] = __hadd2(Tacc[0][im][jn][1], mhi);
                        Tacc[1][im][jn][0] = __hsub2(Tacc[1][im][jn][0], mlo);
                        Tacc[1][im][jn][1] = __hsub2(Tacc[1][im][jn][1], mhi);
                    } else {
                        Tacc[1][im][jn][0] = __hsub2(Tacc[1][im][jn][0], mlo);
                        Tacc[1][im][jn][1] = __hsub2(Tacc[1][im][jn][1], mhi);
                    }
                    acc[im][jn][0] = 0.0f; acc[im][jn][1] = 0.0f;
                    acc[im][jn][2] = 0.0f; acc[im][jn][3] = 0.0f;
                }
        }
    }

    // ---- epilogue: write T0, T1 (fp16) to Tw[(b*2+p)][tile][o] ----
    const int g = lane >> 2;
    #pragma unroll
    for (int p = 0; p < 2; p++) {
        __half* tw = Tw + (size_t)(bfix * 2 + p) * TILEC;
        #pragma unroll
        for (int jn = 0; jn < 4; jn++) {
            const int n = n0 + wn + jn * 8 + (lane & 3) * 2;
            #pragma unroll
            for (int im = 0; im < 2; im++) {
                const int mrow = m0 + wm + im * 16 + g;
                *(__half2*)&tw[(size_t)mrow * NDIM + n]       = Tacc[p][im][jn][0];
                *(__half2*)&tw[(size_t)(mrow + 8) * NDIM + n] = Tacc[p][im][jn][1];
            }
        }
    }
}

// ---------------------------------------------------------------------------
// Kernel 5: output column-combine Y_pq = sum_b A_q[b] T_pb + bias, 4 o/thread
// ---------------------------------------------------------------------------
__global__ __launch_bounds__(256) void output_transform_kernel(const float* __restrict__ bias,
                                                               float* __restrict__ out)
{
    const int tid  = threadIdx.x;
    const int tile = blockIdx.x * 4 + (tid >> 6);
    const int o    = (tid & 63) * 4;

    const int b  = tile >> 10;
    const int ty = (tile >> 5) & 31;
    const int tx = tile & 31;

    float4 tv[4][2];
    #pragma unroll
    for (int bb = 0; bb < 4; bb++)
        #pragma unroll
        for (int p = 0; p < 2; p++) {
            const uint2 u = *(const uint2*)&Tw[(size_t)(bb * 2 + p) * TILEC + (size_t)tile * 256 + o];
            const float2 lo = __half22float2(*(const __half2*)&u.x);
            const float2 hi = __half22float2(*(const __half2*)&u.y);
            tv[bb][p] = make_float4(lo.x, lo.y, hi.x, hi.y);
        }

    const float4 bv = *(const float4*)&bias[o];
    float4 Y00 = f4add(f4add(f4add(tv[0][0], tv[1][0]), tv[2][0]), bv);
    float4 Y01 = f4add(f4sub(f4sub(tv[1][0], tv[2][0]), tv[3][0]), bv);
    float4 Y10 = f4add(f4add(f4add(tv[0][1], tv[1][1]), tv[2][1]), bv);
    float4 Y11 = f4add(f4sub(f4sub(tv[1][1], tv[2][1]), tv[3][1]), bv);

    const int y0 = 2 * ty, x0 = 2 * tx;
    float* obase = out + ((size_t)b * H_ * W_) * NDIM + o;
    *(float4*)&obase[((size_t)y0 * W_ + x0) * NDIM]           = Y00;
    *(float4*)&obase[((size_t)y0 * W_ + x0 + 1) * NDIM]       = Y01;
    *(float4*)&obase[((size_t)(y0 + 1) * W_ + x0) * NDIM]     = Y10;
    *(float4*)&obase[((size_t)(y0 + 1) * W_ + x0 + 1) * NDIM] = Y11;
}

// ---------------------------------------------------------------------------
// Launch: fork fold+wtrans onto a side stream so they overlap with the
// (independent) input transform; join before the GEMM. Streams/events are
// host objects (no device memory); the fork/join is the standard
// capture-compatible event pattern. Handles are intentionally not destroyed
// while capture may be active (kernel_launch is called only a few times).
// ---------------------------------------------------------------------------
extern "C" void kernel_launch(void* const* d_in, const int* in_sizes, int n_in,
                              void* d_out, int out_size)
{
    const float* grid = (const float*)d_in[0];
    const float* Wd   = (const float*)d_in[1];
    const float* Wc   = (const float*)d_in[2];
    const float* bc   = (const float*)d_in[3];
    float* out        = (float*)d_out;

    cudaFuncSetAttribute(wino_gemm_T, cudaFuncAttributeMaxDynamicSharedMemorySize, SM_TOTAL);

    cudaStream_t s2;
    cudaEvent_t eFork, eJoin;
    cudaStreamCreateWithFlags(&s2, cudaStreamNonBlocking);
    cudaEventCreateWithFlags(&eFork, cudaEventDisableTiming);
    cudaEventCreateWithFlags(&eJoin, cudaEventDisableTiming);

    // fork: weight path on s2, input transform on the main (capture) stream
    cudaEventRecord(eFork, 0);
    cudaStreamWaitEvent(s2, eFork, 0);
    fold_weights_kernel<<<128, 256, 0, s2>>>(Wd, Wc);
    weight_transform_kernel<<<256, 256, 0, s2>>>();
    input_transform_kernel<<<NTILES / 4, 256>>>(grid);

    // join: GEMM needs both U_buf (s2) and V_buf (main)
    cudaEventRecord(eJoin, s2);
    cudaStreamWaitEvent(0, eJoin, 0);

    wino_gemm_T<<<(NTILES / BM) * 2 * 4, 256, SM_TOTAL>>>();
    output_transform_kernel<<<NTILES / 4, 256>>>(bc, out);
}